// round 1
// baseline (speedup 1.0000x reference)
#include <cuda_runtime.h>
#include <math.h>

// ---------------- problem constants ----------------
#define S      31
#define HW     (S*S)          // 961
#define B      256
#define HDC    4096
#define RBF    5
#define MODES  16
#define STEPS  8
#define NROWS  (RBF*5*HW)     // 24025 reduction rows of 4096 floats
#define NSLOTS (5*HDC)        // 20480 scatter slots (batch 0 only)

// ---------------- device scratch (no allocation allowed) ----------------
__device__ float g_mp [NROWS];
__device__ float g_mp2[NROWS];
__device__ int   g_lastidx[NSLOTS];
__device__ float g_hdcsum[8];
__device__ float g_dataSum[HW];
__device__ float g_out0[5*HW];
__device__ float g_outg[5*HW];

// ================= Kernel A: mean / mean-sq over HDC axis =================
// rbf_probes layout (r,d,h,w,n): row = (r*5+d)*961 + (h*31+w), 4096 contiguous.
__global__ void probe_reduce_kernel(const float* __restrict__ probes)
{
    const int row = blockIdx.x;
    const float4* __restrict__ p =
        reinterpret_cast<const float4*>(probes) + (size_t)row * 1024;

    float s = 0.f, s2 = 0.f;
#pragma unroll
    for (int i = 0; i < 4; i++) {
        float4 v = p[threadIdx.x + i * 256];
        s  += (v.x + v.y) + (v.z + v.w);
        s2 += v.x*v.x + v.y*v.y + v.z*v.z + v.w*v.w;
    }
#pragma unroll
    for (int o = 16; o; o >>= 1) {
        s  += __shfl_down_sync(0xffffffffu, s,  o);
        s2 += __shfl_down_sync(0xffffffffu, s2, o);
    }
    __shared__ float ws[8], ws2[8];
    const int wid = threadIdx.x >> 5, lane = threadIdx.x & 31;
    if (lane == 0) { ws[wid] = s; ws2[wid] = s2; }
    __syncthreads();
    if (threadIdx.x == 0) {
        float a = 0.f, b = 0.f;
#pragma unroll
        for (int i = 0; i < 8; i++) { a += ws[i]; b += ws2[i]; }
        g_mp [row] = a * (1.f / 4096.f);
        g_mp2[row] = b * (1.f / 4096.f);
    }
}

// ================= Kernel B1: scatter sums + time encoding + dataSum ======
// last-write-wins scatter (matches sequential flat[idx]=sign semantics)
__global__ void prep_kernel(const int*   __restrict__ nzi,
                            const int*   __restrict__ signs,
                            int nnz,
                            const float* __restrict__ din,      // (B,124,31), use b=0
                            const float* __restrict__ sin_in,   // (B,31,31),  use b=0
                            const float* __restrict__ t_in_arr,
                            const float* __restrict__ t_out_arr,
                            const float* __restrict__ ctw,      // (5,16)
                            const float* __restrict__ ctb)      // (5,)
{
    const int tid = threadIdx.x;   // 256 threads, 1 block

    for (int i = tid; i < NSLOTS; i += 256) g_lastidx[i] = -1;
    __syncthreads();
    for (int i = tid; i < nnz; i += 256) {
        int slot = nzi[i];
        if (slot >= 0 && slot < NSLOTS) atomicMax(&g_lastidx[slot], i);
    }
    __syncthreads();

    __shared__ float ssum[5];
    __shared__ float ste[5];
    if (tid < 5) ssum[tid] = 0.f;
    __syncthreads();

    for (int sl = tid; sl < NSLOTS; sl += 256) {
        int li = g_lastidx[sl];
        if (li >= 0) {
            float v = (float)(signs[li] * 2 - 1);
            atomicAdd(&ssum[sl >> 12], v);   // sl / 4096 -> channel
        }
    }

    if (tid == 0) {
        // sinusoidal time encoding for batch 0 only (only batch 0 matters)
        float tin  = t_in_arr[0]  * 0.01f;
        float tout = t_out_arr[0] * 0.01f;
        float pe[MODES];
#pragma unroll
        for (int i = 0; i < MODES; i++) {
            float div  = powf(10000.0f, 2.0f * (float)(i / 2) / (float)MODES);
            float ain  = tin  / div;
            float aout = tout / div;
            pe[i] = (i % 2 == 0) ? 0.5f * (sinf(ain) + cosf(ain))
                                 : 0.5f * (cosf(ain) + sinf(aout));
        }
#pragma unroll
        for (int r = 0; r < 5; r++) {
            float a = ctb[r];
#pragma unroll
            for (int m = 0; m < MODES; m++) a += pe[m] * ctw[r * MODES + m];
            ste[r] = tanhf(a);
        }
    }
    __syncthreads();

    if (tid < 5) g_hdcsum[tid] = ssum[tid];

    // dataSum0[h,w] = sum_c data0[c,h,w] * (1 + te[c])
    for (int p = tid; p < HW; p += 256) {
        int h = p / S, w = p % S;
        float acc = 0.f;
#pragma unroll
        for (int c = 0; c < 4; c++)
            acc += din[(size_t)(c * S + h) * S + w] * (1.0f + ste[c]);
        acc += sin_in[p] * (1.0f + ste[4]);
        g_dataSum[p] = acc;
    }
}

// ================= Kernel B2: RBF distances + 8-step NCA + out conv =======
// blockIdx.x == 0 : batch-0 state,  blockIdx.x == 1 : generic state (proj=0)
__global__ __launch_bounds__(1024, 1)
void nca_kernel(const float* __restrict__ c3w,   // (5,)
                const float* __restrict__ c3b,   // scalar
                const float* __restrict__ ncaw,  // (5,5,3,3)
                const float* __restrict__ ncab,  // (5,)
                const float* __restrict__ spike, // (8,)
                const float* __restrict__ outw,  // (5,5)
                const float* __restrict__ outb)  // (5,)
{
    __shared__ float hA[5 * HW];
    __shared__ float hB[5 * HW];
    __shared__ float w9[225], bb[5], sp[8], ow[25], ob[5], c3[5];
    __shared__ float c3bS;

    const int  tid = threadIdx.x;          // 1024
    const bool gen = (blockIdx.x == 1);

    if (tid < 225) w9[tid] = ncaw[tid];
    if (tid < 25)  ow[tid] = outw[tid];
    if (tid < 8)   sp[tid] = spike[tid];
    if (tid < 5) { bb[tid] = ncab[tid]; ob[tid] = outb[tid]; c3[tid] = c3w[tid]; }
    if (tid == 0) c3bS = c3b[0];
    __syncthreads();

    const float csum = c3[0] + c3[1] + c3[2] + c3[3] + c3[4];

    // x = tanh( sum_r c3[r]*(mp2 - 2*proj*mp + proj^2) + c3b )
    for (int i = tid; i < 5 * HW; i += 1024) {
        int d = i / HW, p = i % HW;
        float a = 0.f, bm = 0.f;
#pragma unroll
        for (int r = 0; r < 5; r++) {
            int ri = (r * 5 + d) * HW + p;
            a  += c3[r] * g_mp2[ri];
            bm += c3[r] * g_mp [ri];
        }
        float proj = gen ? 0.f : (g_hdcsum[d] * g_dataSum[p]);
        hA[i] = tanhf(a - 2.f * proj * bm + proj * proj * csum + c3bS);
    }
    __syncthreads();

    float* cur = hA;
    float* nxt = hB;
#pragma unroll
    for (int st = 0; st < STEPS; st++) {
        float ps = sp[st];
        for (int i = tid; i < 5 * HW; i += 1024) {
            int c = i / HW, p = i % HW;
            int h = p / S,  wq = p % S;
            float y = bb[c];
#pragma unroll
            for (int ci = 0; ci < 5; ci++) {
                const float* base = cur + ci * HW;
                const float* wr   = w9 + (c * 5 + ci) * 9;
#pragma unroll
                for (int kh = 0; kh < 3; kh++) {
                    int hh = h + kh - 1;
                    if (hh < 0 || hh >= S) continue;
#pragma unroll
                    for (int kw = 0; kw < 3; kw++) {
                        int ww = wq + kw - 1;
                        if (ww < 0 || ww >= S) continue;
                        y += wr[kh * 3 + kw] * base[hh * S + ww];
                    }
                }
            }
            nxt[i] = cur[i] + tanhf(y) * ps;
        }
        __syncthreads();
        float* t = cur; cur = nxt; nxt = t;
    }

    float* dst = gen ? g_outg : g_out0;
    for (int i = tid; i < 5 * HW; i += 1024) {
        int o = i / HW, p = i % HW;
        float acc = ob[o];
#pragma unroll
        for (int c = 0; c < 5; c++) acc += ow[o * 5 + c] * cur[c * HW + p];
        dst[i] = acc;
    }
}

// ================= Kernel C: broadcast to (5, B, 31, 31) output ===========
__global__ void writeout_kernel(float* __restrict__ out, int total)
{
    int idx = blockIdx.x * blockDim.x + threadIdx.x;
    if (idx >= total) return;
    int o   = idx / (B * HW);
    int rem = idx - o * (B * HW);
    int b   = rem / HW;
    int p   = rem - b * HW;
    out[idx] = (b == 0) ? g_out0[o * HW + p] : g_outg[o * HW + p];
}

// =================================== launch ================================
extern "C" void kernel_launch(void* const* d_in, const int* in_sizes, int n_in,
                              void* d_out, int out_size)
{
    const float* data_input  = (const float*)d_in[0];
    const float* structure   = (const float*)d_in[1];
    const float* meta_in     = (const float*)d_in[2];
    const float* meta_out    = (const float*)d_in[3];
    const float* spiking     = (const float*)d_in[4];
    const int*   nz_indices  = (const int*)  d_in[5];
    const int*   signs_raw   = (const int*)  d_in[6];
    const float* rbf_probes  = (const float*)d_in[7];
    const float* ct_w        = (const float*)d_in[8];
    const float* ct_b        = (const float*)d_in[9];
    const float* c3_w        = (const float*)d_in[10];
    const float* c3_b        = (const float*)d_in[11];
    const float* nca_w       = (const float*)d_in[12];
    const float* nca_b       = (const float*)d_in[13];
    const float* out_w       = (const float*)d_in[14];
    const float* out_b       = (const float*)d_in[15];
    float* out = (float*)d_out;

    const int nnz = in_sizes[5];

    probe_reduce_kernel<<<NROWS, 256>>>(rbf_probes);
    prep_kernel<<<1, 256>>>(nz_indices, signs_raw, nnz,
                            data_input, structure, meta_in, meta_out,
                            ct_w, ct_b);
    nca_kernel<<<2, 1024>>>(c3_w, c3_b, nca_w, nca_b, spiking, out_w, out_b);

    int total = out_size;
    writeout_kernel<<<(total + 255) / 256, 256>>>(out, total);
}

// round 2
// speedup vs baseline: 3.1795x; 3.1795x over previous
#include <cuda_runtime.h>
#include <math.h>

// ---------------- problem constants ----------------
#define S      31
#define HW     (S*S)          // 961
#define B      256
#define HDC    4096
#define RBF    5
#define MODES  16
#define STEPS  8
#define NROWS  (RBF*5*HW)     // 24025 reduction rows of 4096 floats
#define NSLOTS (5*HDC)        // 20480 scatter slots (batch 0 only)

// ---------------- device scratch (no allocation allowed) ----------------
__device__ float g_mp [NROWS];
__device__ float g_mp2[NROWS];
__device__ int   g_lastidx[NSLOTS];
__device__ float g_hdcsum[8];
__device__ float g_te[5];
__device__ float g_dataSum[HW];
__device__ float g_out0[5*HW];
__device__ float g_outg[5*HW];

// ================= Kernel A: mean / mean-sq over HDC axis =================
// One warp per row (4096 contiguous floats). 32 float4 loads per lane,
// fully independent -> deep MLP, pure warp-shuffle reduction.
__global__ __launch_bounds__(256)
void probe_reduce_kernel(const float* __restrict__ probes)
{
    const int gwarp = (blockIdx.x * blockDim.x + threadIdx.x) >> 5;
    const int lane  = threadIdx.x & 31;
    if (gwarp >= NROWS) return;

    const float4* __restrict__ p =
        reinterpret_cast<const float4*>(probes) + (size_t)gwarp * 1024;

    float s = 0.f, s2 = 0.f;
#pragma unroll
    for (int i = 0; i < 32; i++) {
        float4 v = p[lane + i * 32];
        s  += (v.x + v.y) + (v.z + v.w);
        s2 += (v.x*v.x + v.y*v.y) + (v.z*v.z + v.w*v.w);
    }
#pragma unroll
    for (int o = 16; o; o >>= 1) {
        s  += __shfl_down_sync(0xffffffffu, s,  o);
        s2 += __shfl_down_sync(0xffffffffu, s2, o);
    }
    if (lane == 0) {
        g_mp [gwarp] = s  * (1.f / 4096.f);
        g_mp2[gwarp] = s2 * (1.f / 4096.f);
    }
}

// ================= Kernel P1: init scratch + time encoding + dataSum ======
__global__ void init_kernel(const float* __restrict__ din,      // (B,124,31)
                            const float* __restrict__ sin_in,   // (B,31,31)
                            const float* __restrict__ t_in_arr,
                            const float* __restrict__ t_out_arr,
                            const float* __restrict__ ctw,      // (5,16)
                            const float* __restrict__ ctb)      // (5,)
{
    const int tid = threadIdx.x;
    const int bid = blockIdx.x;

    if (bid < 80) {
        int i = bid * 256 + tid;
        if (i < NSLOTS) g_lastidx[i] = -1;
        if (bid == 0 && tid < 8) g_hdcsum[tid] = 0.f;
        return;
    }

    // bid == 80: time encoding + weighted data sum (batch 0 only)
    __shared__ float ste[5];
    if (tid == 0) {
        float tin  = t_in_arr[0]  * 0.01f;
        float tout = t_out_arr[0] * 0.01f;
        float pe[MODES];
#pragma unroll
        for (int i = 0; i < MODES; i++) {
            float div  = powf(10000.0f, 2.0f * (float)(i / 2) / (float)MODES);
            float ain  = tin  / div;
            float aout = tout / div;
            pe[i] = (i % 2 == 0) ? 0.5f * (sinf(ain) + cosf(ain))
                                 : 0.5f * (cosf(ain) + sinf(aout));
        }
#pragma unroll
        for (int r = 0; r < 5; r++) {
            float a = ctb[r];
#pragma unroll
            for (int m = 0; m < MODES; m++) a += pe[m] * ctw[r * MODES + m];
            ste[r] = tanhf(a);
            g_te[r] = ste[r];
        }
    }
    __syncthreads();

    for (int p = tid; p < HW; p += 256) {
        int h = p / S, w = p % S;
        float acc = 0.f;
#pragma unroll
        for (int c = 0; c < 4; c++)
            acc += din[(size_t)(c * S + h) * S + w] * (1.0f + ste[c]);
        acc += sin_in[p] * (1.0f + ste[4]);
        g_dataSum[p] = acc;
    }
}

// ================= Kernel P2: last-write-wins scatter =====================
__global__ void scatter_kernel(const int* __restrict__ nzi, int nnz)
{
    int i = blockIdx.x * blockDim.x + threadIdx.x;
    if (i >= nnz) return;
    int slot = nzi[i];
    if (slot >= 0 && slot < NSLOTS) atomicMax(&g_lastidx[slot], i);
}

// ================= Kernel P3: per-channel sign sums =======================
__global__ void chansum_kernel(const int* __restrict__ signs)
{
    __shared__ float part[5];
    const int tid = threadIdx.x;
    if (tid < 5) part[tid] = 0.f;
    __syncthreads();

    int sl = blockIdx.x * blockDim.x + tid;
    if (sl < NSLOTS) {
        int li = g_lastidx[sl];
        if (li >= 0) {
            float v = (float)(signs[li] * 2 - 1);
            atomicAdd(&part[sl >> 12], v);
        }
    }
    __syncthreads();
    if (tid < 5 && part[tid] != 0.f) atomicAdd(&g_hdcsum[tid], part[tid]);
}

// ================= Kernel B2: RBF distances + 8-step NCA + out conv =======
// blockIdx.x == 0 : batch-0 state,  blockIdx.x == 1 : generic state (proj=0)
__global__ __launch_bounds__(1024, 1)
void nca_kernel(const float* __restrict__ c3w,   // (5,)
                const float* __restrict__ c3b,   // scalar
                const float* __restrict__ ncaw,  // (5,5,3,3)
                const float* __restrict__ ncab,  // (5,)
                const float* __restrict__ spike, // (8,)
                const float* __restrict__ outw,  // (5,5)
                const float* __restrict__ outb)  // (5,)
{
    __shared__ float hA[5 * HW];
    __shared__ float hB[5 * HW];
    __shared__ float w9[225], bb[5], sp[8], ow[25], ob[5], c3[5];
    __shared__ float c3bS;

    const int  tid = threadIdx.x;          // 1024
    const bool gen = (blockIdx.x == 1);

    if (tid < 225) w9[tid] = ncaw[tid];
    if (tid < 25)  ow[tid] = outw[tid];
    if (tid < 8)   sp[tid] = spike[tid];
    if (tid < 5) { bb[tid] = ncab[tid]; ob[tid] = outb[tid]; c3[tid] = c3w[tid]; }
    if (tid == 0) c3bS = c3b[0];
    __syncthreads();

    const float csum = c3[0] + c3[1] + c3[2] + c3[3] + c3[4];

    // x = tanh( sum_r c3[r]*(mp2 - 2*proj*mp + proj^2) + c3b )
    for (int i = tid; i < 5 * HW; i += 1024) {
        int d = i / HW, p = i % HW;
        float a = 0.f, bm = 0.f;
#pragma unroll
        for (int r = 0; r < 5; r++) {
            int ri = (r * 5 + d) * HW + p;
            a  += c3[r] * g_mp2[ri];
            bm += c3[r] * g_mp [ri];
        }
        float proj = gen ? 0.f : (g_hdcsum[d] * g_dataSum[p]);
        hA[i] = tanhf(a - 2.f * proj * bm + proj * proj * csum + c3bS);
    }
    __syncthreads();

    float* cur = hA;
    float* nxt = hB;
#pragma unroll
    for (int st = 0; st < STEPS; st++) {
        float ps = sp[st];
        for (int i = tid; i < 5 * HW; i += 1024) {
            int c = i / HW, p = i % HW;
            int h = p / S,  wq = p % S;
            float y = bb[c];
#pragma unroll
            for (int ci = 0; ci < 5; ci++) {
                const float* base = cur + ci * HW;
                const float* wr   = w9 + (c * 5 + ci) * 9;
#pragma unroll
                for (int kh = 0; kh < 3; kh++) {
                    int hh = h + kh - 1;
                    if (hh < 0 || hh >= S) continue;
#pragma unroll
                    for (int kw = 0; kw < 3; kw++) {
                        int ww = wq + kw - 1;
                        if (ww < 0 || ww >= S) continue;
                        y += wr[kh * 3 + kw] * base[hh * S + ww];
                    }
                }
            }
            nxt[i] = cur[i] + tanhf(y) * ps;
        }
        __syncthreads();
        float* t = cur; cur = nxt; nxt = t;
    }

    float* dst = gen ? g_outg : g_out0;
    for (int i = tid; i < 5 * HW; i += 1024) {
        int o = i / HW, p = i % HW;
        float acc = ob[o];
#pragma unroll
        for (int c = 0; c < 5; c++) acc += ow[o * 5 + c] * cur[c * HW + p];
        dst[i] = acc;
    }
}

// ================= Kernel C: broadcast to (5, B, 31, 31) output ===========
__global__ void writeout_kernel(float* __restrict__ out, int total)
{
    int idx = blockIdx.x * blockDim.x + threadIdx.x;
    if (idx >= total) return;
    int o   = idx / (B * HW);
    int rem = idx - o * (B * HW);
    int b   = rem / HW;
    int p   = rem - b * HW;
    out[idx] = (b == 0) ? g_out0[o * HW + p] : g_outg[o * HW + p];
}

// =================================== launch ================================
extern "C" void kernel_launch(void* const* d_in, const int* in_sizes, int n_in,
                              void* d_out, int out_size)
{
    const float* data_input  = (const float*)d_in[0];
    const float* structure   = (const float*)d_in[1];
    const float* meta_in     = (const float*)d_in[2];
    const float* meta_out    = (const float*)d_in[3];
    const float* spiking     = (const float*)d_in[4];
    const int*   nz_indices  = (const int*)  d_in[5];
    const int*   signs_raw   = (const int*)  d_in[6];
    const float* rbf_probes  = (const float*)d_in[7];
    const float* ct_w        = (const float*)d_in[8];
    const float* ct_b        = (const float*)d_in[9];
    const float* c3_w        = (const float*)d_in[10];
    const float* c3_b        = (const float*)d_in[11];
    const float* nca_w       = (const float*)d_in[12];
    const float* nca_b       = (const float*)d_in[13];
    const float* out_w       = (const float*)d_in[14];
    const float* out_b       = (const float*)d_in[15];
    float* out = (float*)d_out;

    const int nnz = in_sizes[5];

    // Kernel A: 1 warp per row, 8 warps per block
    int nblk_a = (NROWS * 32 + 255) / 256;
    probe_reduce_kernel<<<nblk_a, 256>>>(rbf_probes);

    // Prep pipeline (parallelized)
    init_kernel<<<81, 256>>>(data_input, structure, meta_in, meta_out, ct_w, ct_b);
    scatter_kernel<<<(nnz + 255) / 256, 256>>>(nz_indices, nnz);
    chansum_kernel<<<(NSLOTS + 255) / 256, 256>>>(signs_raw);

    nca_kernel<<<2, 1024>>>(c3_w, c3_b, nca_w, nca_b, spiking, out_w, out_b);

    writeout_kernel<<<(out_size + 255) / 256, 256>>>(out, out_size);
}

// round 3
// speedup vs baseline: 3.4947x; 1.0991x over previous
#include <cuda_runtime.h>
#include <math.h>

// ---------------- problem constants ----------------
#define S      31
#define HW     (S*S)          // 961
#define B      256
#define HDC    4096
#define RBF    5
#define MODES  16
#define STEPS  8
#define NROWS  (RBF*5*HW)     // 24025 reduction rows of 4096 floats
#define NSLOTS (5*HDC)        // 20480 scatter slots (batch 0 only)

// ---------------- device scratch (no allocation; zero-initialized) --------
__device__ float g_mp [NROWS];
__device__ float g_mp2[NROWS];
__device__ int   g_pack[NSLOTS];   // 0 = empty; else ((i+1)<<1)|sign
__device__ float g_out0[5*HW];
__device__ float g_outg[5*HW];

// ================= Kernel A: mean / mean-sq over HDC axis =================
// One warp per row (4096 contiguous floats). 32 float4 loads per lane,
// fully independent -> deep MLP, pure warp-shuffle reduction.
__global__ __launch_bounds__(256)
void probe_reduce_kernel(const float* __restrict__ probes)
{
    const int gwarp = (blockIdx.x * blockDim.x + threadIdx.x) >> 5;
    const int lane  = threadIdx.x & 31;
    if (gwarp >= NROWS) return;

    const float4* __restrict__ p =
        reinterpret_cast<const float4*>(probes) + (size_t)gwarp * 1024;

    float s = 0.f, s2 = 0.f;
#pragma unroll
    for (int i = 0; i < 32; i++) {
        float4 v = p[lane + i * 32];
        s  += (v.x + v.y) + (v.z + v.w);
        s2 += (v.x*v.x + v.y*v.y) + (v.z*v.z + v.w*v.w);
    }
#pragma unroll
    for (int o = 16; o; o >>= 1) {
        s  += __shfl_down_sync(0xffffffffu, s,  o);
        s2 += __shfl_down_sync(0xffffffffu, s2, o);
    }
    if (lane == 0) {
        g_mp [gwarp] = s  * (1.f / 4096.f);
        g_mp2[gwarp] = s2 * (1.f / 4096.f);
    }
}

// ================= Kernel P: last-write-wins scatter (packed) =============
// packed = ((i+1)<<1) | sign  -> atomicMax picks the highest i; sign rides
// along in the LSB. 0 means "never written" (globals are zero-init and the
// consumer resets slots to 0, so this is replay-safe).
__global__ void scatter_kernel(const int* __restrict__ nzi,
                               const int* __restrict__ signs, int nnz)
{
    int i = blockIdx.x * blockDim.x + threadIdx.x;
    if (i >= nnz) return;
    int slot = nzi[i];
    if (slot >= 0 && slot < NSLOTS) {
        int packed = ((i + 1) << 1) | (signs[i] & 1);
        atomicMax(&g_pack[slot], packed);
    }
}

// ================= Kernel B: chansum + te + RBF + 8-step NCA + out conv ===
// blockIdx.x == 0 : batch-0 state (does chansum/te/dataSum prep too)
// blockIdx.x == 1 : generic state (proj = 0)
__global__ __launch_bounds__(1024, 1)
void nca_kernel(const float* __restrict__ din,      // (B,124,31), batch 0
                const float* __restrict__ sin_in,   // (B,31,31),  batch 0
                const float* __restrict__ t_in_arr,
                const float* __restrict__ t_out_arr,
                const float* __restrict__ ctw,      // (5,16)
                const float* __restrict__ ctb,      // (5,)
                const float* __restrict__ c3w,      // (5,)
                const float* __restrict__ c3b,      // scalar
                const float* __restrict__ ncaw,     // (5,5,3,3)
                const float* __restrict__ ncab,     // (5,)
                const float* __restrict__ spike,    // (8,)
                const float* __restrict__ outw,     // (5,5)
                const float* __restrict__ outb)     // (5,)
{
    __shared__ float hA[5 * HW];
    __shared__ float hB[5 * HW];
    __shared__ float sDS[HW];                 // dataSum (block 0 only)
    __shared__ float w9[225], bb[5], sp[8], ow[25], ob[5], c3[5];
    __shared__ float sHdc[5];
    __shared__ float c3bS;
    __shared__ float red[32];

    const int  tid  = threadIdx.x;            // 1024
    const int  lane = tid & 31, wid = tid >> 5;
    const bool gen  = (blockIdx.x == 1);

    if (tid < 225) w9[tid] = ncaw[tid];
    if (tid < 25)  ow[tid] = outw[tid];
    if (tid < 8)   sp[tid] = spike[tid];
    if (tid < 5) { bb[tid] = ncab[tid]; ob[tid] = outb[tid]; c3[tid] = c3w[tid]; }
    if (tid == 0) c3bS = c3b[0];

    if (!gen) {
        // ---- per-channel sign sums from packed scatter array (+ reset) ----
        float loc[5] = {0.f, 0.f, 0.f, 0.f, 0.f};
#pragma unroll
        for (int ch = 0; ch < 5; ch++) {
            for (int sl = ch * HDC + tid; sl < (ch + 1) * HDC; sl += 1024) {
                int v = g_pack[sl];
                if (v) {
                    g_pack[sl] = 0;                       // self-clean for replay
                    loc[ch] += (float)((v & 1) * 2 - 1);
                }
            }
        }
#pragma unroll
        for (int ch = 0; ch < 5; ch++) {
            float a = loc[ch];
#pragma unroll
            for (int o = 16; o; o >>= 1) a += __shfl_down_sync(0xffffffffu, a, o);
            if (lane == 0) red[wid] = a;
            __syncthreads();
            if (tid == 0) {
                float t = 0.f;
#pragma unroll
                for (int k = 0; k < 32; k++) t += red[k];
                sHdc[ch] = t;
            }
            __syncthreads();
        }

        // ---- time encoding (thread 0) ----
        __shared__ float ste[5];
        if (tid == 0) {
            float tin  = t_in_arr[0]  * 0.01f;
            float tout = t_out_arr[0] * 0.01f;
            float pe[MODES];
#pragma unroll
            for (int i = 0; i < MODES; i++) {
                float div  = powf(10000.0f, 2.0f * (float)(i / 2) / (float)MODES);
                pe[i] = (i % 2 == 0) ? 0.5f * (sinf(tin / div) + cosf(tin / div))
                                     : 0.5f * (cosf(tin / div) + sinf(tout / div));
            }
#pragma unroll
            for (int r = 0; r < 5; r++) {
                float a = ctb[r];
#pragma unroll
                for (int m = 0; m < MODES; m++) a += pe[m] * ctw[r * MODES + m];
                ste[r] = tanhf(a);
            }
        }
        __syncthreads();

        // ---- dataSum[p] = sum_c data0[c,h,w] * (1 + te[c]) ----
        for (int p = tid; p < HW; p += 1024) {
            int h = p / S, w = p % S;
            float acc = 0.f;
#pragma unroll
            for (int c = 0; c < 4; c++)
                acc += din[(size_t)(c * S + h) * S + w] * (1.0f + ste[c]);
            acc += sin_in[p] * (1.0f + ste[4]);
            sDS[p] = acc;
        }
    }
    __syncthreads();

    const float csum = c3[0] + c3[1] + c3[2] + c3[3] + c3[4];

    // x = tanh( sum_r c3[r]*(mp2 - 2*proj*mp + proj^2) + c3b )
    for (int i = tid; i < 5 * HW; i += 1024) {
        int d = i / HW, p = i % HW;
        float a = 0.f, bm = 0.f;
#pragma unroll
        for (int r = 0; r < 5; r++) {
            int ri = (r * 5 + d) * HW + p;
            a  += c3[r] * g_mp2[ri];
            bm += c3[r] * g_mp [ri];
        }
        float proj = gen ? 0.f : (sHdc[d] * sDS[p]);
        hA[i] = tanhf(a - 2.f * proj * bm + proj * proj * csum + c3bS);
    }
    __syncthreads();

    float* cur = hA;
    float* nxt = hB;
#pragma unroll
    for (int st = 0; st < STEPS; st++) {
        float ps = sp[st];
        for (int i = tid; i < 5 * HW; i += 1024) {
            int c = i / HW, p = i % HW;
            int h = p / S,  wq = p % S;
            float y = bb[c];
#pragma unroll
            for (int ci = 0; ci < 5; ci++) {
                const float* base = cur + ci * HW;
                const float* wr   = w9 + (c * 5 + ci) * 9;
#pragma unroll
                for (int kh = 0; kh < 3; kh++) {
                    int hh = h + kh - 1;
                    if (hh < 0 || hh >= S) continue;
#pragma unroll
                    for (int kw = 0; kw < 3; kw++) {
                        int ww = wq + kw - 1;
                        if (ww < 0 || ww >= S) continue;
                        y += wr[kh * 3 + kw] * base[hh * S + ww];
                    }
                }
            }
            nxt[i] = cur[i] + tanhf(y) * ps;
        }
        __syncthreads();
        float* t = cur; cur = nxt; nxt = t;
    }

    float* dst = gen ? g_outg : g_out0;
    for (int i = tid; i < 5 * HW; i += 1024) {
        int o = i / HW, p = i % HW;
        float acc = ob[o];
#pragma unroll
        for (int c = 0; c < 5; c++) acc += ow[o * 5 + c] * cur[c * HW + p];
        dst[i] = acc;
    }
}

// ================= Kernel C: broadcast to (5, B, 31, 31) output ===========
__global__ __launch_bounds__(256)
void writeout_kernel(float* __restrict__ out, int total)
{
    int base = (blockIdx.x * blockDim.x + threadIdx.x) * 4;
    if (base >= total) return;
    int o   = base / (B * HW);
    int rem = base - o * (B * HW);
    int b   = rem / HW;
    int p   = rem - b * HW;
#pragma unroll
    for (int j = 0; j < 4; j++) {
        int idx = base + j;
        if (idx >= total) break;
        const float* src = (b == 0) ? g_out0 : g_outg;
        out[idx] = src[o * HW + p];
        if (++p == HW) { p = 0; if (++b == B) { b = 0; ++o; } }
    }
}

// =================================== launch ================================
extern "C" void kernel_launch(void* const* d_in, const int* in_sizes, int n_in,
                              void* d_out, int out_size)
{
    const float* data_input  = (const float*)d_in[0];
    const float* structure   = (const float*)d_in[1];
    const float* meta_in     = (const float*)d_in[2];
    const float* meta_out    = (const float*)d_in[3];
    const float* spiking     = (const float*)d_in[4];
    const int*   nz_indices  = (const int*)  d_in[5];
    const int*   signs_raw   = (const int*)  d_in[6];
    const float* rbf_probes  = (const float*)d_in[7];
    const float* ct_w        = (const float*)d_in[8];
    const float* ct_b        = (const float*)d_in[9];
    const float* c3_w        = (const float*)d_in[10];
    const float* c3_b        = (const float*)d_in[11];
    const float* nca_w       = (const float*)d_in[12];
    const float* nca_b       = (const float*)d_in[13];
    const float* out_w       = (const float*)d_in[14];
    const float* out_b       = (const float*)d_in[15];
    float* out = (float*)d_out;

    const int nnz = in_sizes[5];

    int nblk_a = (NROWS * 32 + 255) / 256;   // 1 warp per row
    probe_reduce_kernel<<<nblk_a, 256>>>(rbf_probes);

    scatter_kernel<<<(nnz + 255) / 256, 256>>>(nz_indices, signs_raw, nnz);

    nca_kernel<<<2, 1024>>>(data_input, structure, meta_in, meta_out,
                            ct_w, ct_b, c3_w, c3_b, nca_w, nca_b,
                            spiking, out_w, out_b);

    int nquad = (out_size + 3) / 4;
    writeout_kernel<<<(nquad + 255) / 256, 256>>>(out, out_size);
}